// round 1
// baseline (speedup 1.0000x reference)
#include <cuda_runtime.h>
#include <cstdint>

// Problem constants (fixed by the reference setup).
constexpr int B  = 32;
constexpr int H  = 512;
constexpr int W  = 512;
constexpr int HW = H * W;                 // 262144, one channel plane
constexpr int NPIX = B * HW;              // 8,388,608 pixels
constexpr int PIX_PER_THREAD = 4;
constexpr int THREADS = 256;
constexpr int GRID = NPIX / PIX_PER_THREAD / THREADS;   // 8192 blocks
constexpr float INV_COUNT = 1.0f / (2.0f * (float)NPIX); // mean over B*C*H*W

__device__ float g_partials[GRID];

__global__ __launch_bounds__(THREADS)
void cyc_loss_main(const float* __restrict__ fwd, const float* __restrict__ bwd)
{
    const int tid = blockIdx.x * blockDim.x + threadIdx.x;
    const int p0  = tid * PIX_PER_THREAD;          // first pixel of this thread
    const int b   = p0 / HW;
    const int rem = p0 - b * HW;
    const int y   = rem >> 9;                      // /512
    const int x   = rem & 511;                     // %512 ; x%4==0 so 4 pixels share a row

    const float* __restrict__ fw = fwd + (size_t)b * 2 * HW;
    const float* __restrict__ c0 = bwd + (size_t)b * 2 * HW;   // channel 0 plane
    const float* __restrict__ c1 = c0 + HW;                    // channel 1 plane

    const int rowoff = y * W + x;
    const float4 dx4 = *reinterpret_cast<const float4*>(fw + rowoff);
    const float4 dy4 = *reinterpret_cast<const float4*>(fw + HW + rowoff);

    float acc = 0.0f;
    const float dxv[4] = {dx4.x, dx4.y, dx4.z, dx4.w};
    const float dyv[4] = {dy4.x, dy4.y, dy4.z, dy4.w};

#pragma unroll
    for (int i = 0; i < 4; ++i) {
        const float dx = dxv[i];
        const float dy = dyv[i];
        // Border-clamped sample position
        const float gx = fminf(fmaxf((float)(x + i) + dx, 0.0f), (float)(W - 1));
        const float gy = fminf(fmaxf((float)y       + dy, 0.0f), (float)(H - 1));
        const float x0f = floorf(gx);
        const float y0f = floorf(gy);
        const float wx = gx - x0f;
        const float wy = gy - y0f;
        const int x0 = (int)x0f;
        const int y0 = (int)y0f;
        const int x1 = min(x0 + 1, W - 1);
        const int y1 = min(y0 + 1, H - 1);

        const int i00 = y0 * W + x0;
        const int i01 = y0 * W + x1;
        const int i10 = y1 * W + x0;
        const int i11 = y1 * W + x1;

        // Channel 0 taps
        const float a00 = __ldg(c0 + i00);
        const float a01 = __ldg(c0 + i01);
        const float a10 = __ldg(c0 + i10);
        const float a11 = __ldg(c0 + i11);
        // Channel 1 taps
        const float b00 = __ldg(c1 + i00);
        const float b01 = __ldg(c1 + i01);
        const float b10 = __ldg(c1 + i10);
        const float b11 = __ldg(c1 + i11);

        // Bilinear lerp (matches v00*(1-wx)+v01*wx numerically via fma form)
        const float top0 = fmaf(wx, a01 - a00, a00);
        const float bot0 = fmaf(wx, a11 - a10, a10);
        const float s0   = fmaf(wy, bot0 - top0, top0);
        const float top1 = fmaf(wx, b01 - b00, b00);
        const float bot1 = fmaf(wx, b11 - b10, b10);
        const float s1   = fmaf(wy, bot1 - top1, top1);

        const float r0 = dx + s0;
        const float r1 = dy + s1;
        acc = fmaf(r0, r0, acc);
        acc = fmaf(r1, r1, acc);
    }

    // ---- Block reduction (deterministic) ----
    __shared__ float warp_sums[THREADS / 32];
    // warp-level tree
#pragma unroll
    for (int off = 16; off > 0; off >>= 1)
        acc += __shfl_xor_sync(0xFFFFFFFFu, acc, off);

    const int lane = threadIdx.x & 31;
    const int wid  = threadIdx.x >> 5;
    if (lane == 0) warp_sums[wid] = acc;
    __syncthreads();

    if (wid == 0) {
        float v = (lane < THREADS / 32) ? warp_sums[lane] : 0.0f;
#pragma unroll
        for (int off = 4; off > 0; off >>= 1)
            v += __shfl_xor_sync(0xFFFFFFFFu, v, off);
        if (lane == 0) g_partials[blockIdx.x] = v;
    }
}

__global__ __launch_bounds__(1024)
void cyc_loss_reduce(float* __restrict__ out)
{
    // Single block: 1024 threads, each sums GRID/1024 = 8 partials, then tree-reduce.
    float acc = 0.0f;
    for (int i = threadIdx.x; i < GRID; i += 1024)
        acc += g_partials[i];

    __shared__ float warp_sums[32];
#pragma unroll
    for (int off = 16; off > 0; off >>= 1)
        acc += __shfl_xor_sync(0xFFFFFFFFu, acc, off);

    const int lane = threadIdx.x & 31;
    const int wid  = threadIdx.x >> 5;
    if (lane == 0) warp_sums[wid] = acc;
    __syncthreads();

    if (wid == 0) {
        float v = (lane < 32) ? warp_sums[lane] : 0.0f;
#pragma unroll
        for (int off = 16; off > 0; off >>= 1)
            v += __shfl_xor_sync(0xFFFFFFFFu, v, off);
        if (lane == 0) out[0] = v * INV_COUNT;
    }
}

extern "C" void kernel_launch(void* const* d_in, const int* in_sizes, int n_in,
                              void* d_out, int out_size)
{
    const float* fwd = (const float*)d_in[0];   // forward_disp  (B,2,H,W) fp32
    const float* bwd = (const float*)d_in[1];   // backward_disp (B,2,H,W) fp32
    float* out = (float*)d_out;

    cyc_loss_main<<<GRID, THREADS>>>(fwd, bwd);
    cyc_loss_reduce<<<1, 1024>>>(out);
}

// round 3
// speedup vs baseline: 1.1651x; 1.1651x over previous
#include <cuda_runtime.h>
#include <cstdint>

// Problem constants (fixed by the reference setup).
constexpr int B  = 32;
constexpr int H  = 512;
constexpr int W  = 512;
constexpr int HW = H * W;                  // 262144 = 2^18, one channel plane
constexpr int NPIX = B * HW;               // 8,388,608 pixels
constexpr int BATCH_PER_THREAD = 4;        // each thread: same (y,x), 4 batches
constexpr int THREADS = 256;
constexpr int NTHREADS_TOTAL = NPIX / BATCH_PER_THREAD;    // 2,097,152
constexpr int GRID = NTHREADS_TOTAL / THREADS;             // 8192 blocks
constexpr float INV_COUNT = 1.0f / (2.0f * (float)NPIX);   // mean over B*C*H*W

__device__ float g_partials[GRID];
__device__ int   g_count = 0;

__global__ __launch_bounds__(THREADS)
void cyc_loss_fused(const float* __restrict__ fwd, const float* __restrict__ bwd,
                    float* __restrict__ out)
{
    const int t = blockIdx.x * THREADS + threadIdx.x;     // [0, 2^21)
    // b_base in [0,8), pix in [0, HW). Warp lanes -> 32 consecutive x.
    const int b_base = t >> 18;                            // t / HW
    const int pix    = t & (HW - 1);
    const int y      = pix >> 9;                           // /512
    const int x      = pix & 511;

    float acc = 0.0f;

#pragma unroll
    for (int k = 0; k < BATCH_PER_THREAD; ++k) {
        const int b = b_base + (k << 3);                   // b_base + 8k
        const float* __restrict__ fw = fwd + (size_t)b * 2 * HW;
        const float* __restrict__ c0 = bwd + (size_t)b * 2 * HW;
        const float* __restrict__ c1 = c0 + HW;

        const int po = y * W + x;
        const float dx = __ldg(fw + po);
        const float dy = __ldg(fw + HW + po);

        const float gx = fminf(fmaxf((float)x + dx, 0.0f), (float)(W - 1));
        const float gy = fminf(fmaxf((float)y + dy, 0.0f), (float)(H - 1));
        const float x0f = floorf(gx);
        const float y0f = floorf(gy);
        const float wx = gx - x0f;
        const float wy = gy - y0f;
        const int x0 = (int)x0f;
        const int y0 = (int)y0f;
        const int x1 = min(x0 + 1, W - 1);
        const int y1 = min(y0 + 1, H - 1);

        const int i00 = y0 * W + x0;
        const int i01 = y0 * W + x1;
        const int i10 = y1 * W + x0;
        const int i11 = y1 * W + x1;

        const float a00 = __ldg(c0 + i00);
        const float a01 = __ldg(c0 + i01);
        const float a10 = __ldg(c0 + i10);
        const float a11 = __ldg(c0 + i11);
        const float b00 = __ldg(c1 + i00);
        const float b01 = __ldg(c1 + i01);
        const float b10 = __ldg(c1 + i10);
        const float b11 = __ldg(c1 + i11);

        const float top0 = fmaf(wx, a01 - a00, a00);
        const float bot0 = fmaf(wx, a11 - a10, a10);
        const float s0   = fmaf(wy, bot0 - top0, top0);
        const float top1 = fmaf(wx, b01 - b00, b00);
        const float bot1 = fmaf(wx, b11 - b10, b10);
        const float s1   = fmaf(wy, bot1 - top1, top1);

        const float r0 = dx + s0;
        const float r1 = dy + s1;
        acc = fmaf(r0, r0, acc);
        acc = fmaf(r1, r1, acc);
    }

    // ---- Block reduction (deterministic tree) ----
    __shared__ float warp_sums[THREADS / 32];
#pragma unroll
    for (int off = 16; off > 0; off >>= 1)
        acc += __shfl_xor_sync(0xFFFFFFFFu, acc, off);

    const int lane = threadIdx.x & 31;
    const int wid  = threadIdx.x >> 5;
    if (lane == 0) warp_sums[wid] = acc;
    __syncthreads();

    __shared__ bool is_last;
    if (wid == 0) {
        float v = (lane < THREADS / 32) ? warp_sums[lane] : 0.0f;
#pragma unroll
        for (int off = 4; off > 0; off >>= 1)
            v += __shfl_xor_sync(0xFFFFFFFFu, v, off);
        if (lane == 0) {
            __stcg(&g_partials[blockIdx.x], v);    // write-through L2 (skip L1)
            __threadfence();                       // partial visible before count bump
            const int prev = atomicAdd(&g_count, 1);
            is_last = (prev == GRID - 1);
        }
    }
    __syncthreads();

    // ---- Last block performs the final reduction (fixed order -> deterministic) ----
    if (is_last) {
        float v = 0.0f;
        // Fixed traversal order per thread; L1-bypass loads to see other SMs' stores.
        for (int i = threadIdx.x; i < GRID; i += THREADS)
            v += __ldcg(&g_partials[i]);

#pragma unroll
        for (int off = 16; off > 0; off >>= 1)
            v += __shfl_xor_sync(0xFFFFFFFFu, v, off);
        if (lane == 0) warp_sums[wid] = v;
        __syncthreads();

        if (wid == 0) {
            float s = (lane < THREADS / 32) ? warp_sums[lane] : 0.0f;
#pragma unroll
            for (int off = 4; off > 0; off >>= 1)
                s += __shfl_xor_sync(0xFFFFFFFFu, s, off);
            if (lane == 0) {
                out[0] = s * INV_COUNT;
                g_count = 0;                       // reset for next graph replay
            }
        }
    }
}

extern "C" void kernel_launch(void* const* d_in, const int* in_sizes, int n_in,
                              void* d_out, int out_size)
{
    const float* fwd = (const float*)d_in[0];   // forward_disp  (B,2,H,W) fp32
    const float* bwd = (const float*)d_in[1];   // backward_disp (B,2,H,W) fp32
    float* out = (float*)d_out;

    cyc_loss_fused<<<GRID, THREADS>>>(fwd, bwd, out);
}

// round 4
// speedup vs baseline: 1.1732x; 1.0070x over previous
#include <cuda_runtime.h>
#include <cstdint>

// Problem constants (fixed by the reference setup).
constexpr int B  = 32;
constexpr int H  = 512;
constexpr int W  = 512;
constexpr int HW = H * W;                  // 262144 = 2^18, one channel plane
constexpr int NPIX = B * HW;               // 8,388,608 pixels
constexpr int K  = 4;                      // batches per thread
constexpr int THREADS = 256;
constexpr int NTHREADS_TOTAL = NPIX / K;               // 2,097,152
constexpr int GRID = NTHREADS_TOTAL / THREADS;         // 8192 blocks
constexpr float INV_COUNT = 1.0f / (2.0f * (float)NPIX);

__device__ float g_partials[GRID];
__device__ int   g_count = 0;

__global__ __launch_bounds__(THREADS)
void cyc_loss_fused(const float* __restrict__ fwd, const float* __restrict__ bwd,
                    float* __restrict__ out)
{
    const int t = blockIdx.x * THREADS + threadIdx.x;  // [0, 2^21)
    const int b_base = t >> 18;                        // t / HW, in [0,8)
    const int pix    = t & (HW - 1);                   // also == y*W + x
    const int y      = pix >> 9;
    const int x      = pix & 511;

    // ---------- Phase A: issue ALL loads up front (force MLP) ----------
    float dxv[K], dyv[K], wxv[K], wyv[K];
    float a00[K], a01[K], a10[K], a11[K];
    float b00[K], b01[K], b10[K], b11[K];

#pragma unroll
    for (int k = 0; k < K; ++k) {
        const int b = b_base + (k << 3);
        const float* __restrict__ fw = fwd + (size_t)b * 2 * HW;
        dxv[k] = __ldg(fw + pix);
        dyv[k] = __ldg(fw + HW + pix);
    }

#pragma unroll
    for (int k = 0; k < K; ++k) {
        const float gx = fminf(fmaxf((float)x + dxv[k], 0.0f), (float)(W - 1));
        const float gy = fminf(fmaxf((float)y + dyv[k], 0.0f), (float)(H - 1));
        const int x0 = __float2int_rd(gx);
        const int y0 = __float2int_rd(gy);
        wxv[k] = gx - (float)x0;
        wyv[k] = gy - (float)y0;
        const int x1 = min(x0 + 1, W - 1);
        const int y1 = min(y0 + 1, H - 1);
        const int r0 = y0 << 9;
        const int r1 = y1 << 9;
        const int i00 = r0 + x0;
        const int i01 = r0 + x1;
        const int i10 = r1 + x0;
        const int i11 = r1 + x1;

        const int b = b_base + (k << 3);
        const float* __restrict__ c0 = bwd + (size_t)b * 2 * HW;
        const float* __restrict__ c1 = c0 + HW;

        a00[k] = __ldg(c0 + i00);
        a01[k] = __ldg(c0 + i01);
        a10[k] = __ldg(c0 + i10);
        a11[k] = __ldg(c0 + i11);
        b00[k] = __ldg(c1 + i00);
        b01[k] = __ldg(c1 + i01);
        b10[k] = __ldg(c1 + i10);
        b11[k] = __ldg(c1 + i11);
    }

    // ---------- Phase B: math ----------
    float acc = 0.0f;
#pragma unroll
    for (int k = 0; k < K; ++k) {
        const float wx = wxv[k];
        const float wy = wyv[k];
        const float top0 = fmaf(wx, a01[k] - a00[k], a00[k]);
        const float bot0 = fmaf(wx, a11[k] - a10[k], a10[k]);
        const float s0   = fmaf(wy, bot0 - top0, top0);
        const float top1 = fmaf(wx, b01[k] - b00[k], b00[k]);
        const float bot1 = fmaf(wx, b11[k] - b10[k], b10[k]);
        const float s1   = fmaf(wy, bot1 - top1, top1);
        const float r0 = dxv[k] + s0;
        const float r1 = dyv[k] + s1;
        acc = fmaf(r0, r0, acc);
        acc = fmaf(r1, r1, acc);
    }

    // ---------- Block reduction (deterministic tree) ----------
    __shared__ float warp_sums[THREADS / 32];
#pragma unroll
    for (int off = 16; off > 0; off >>= 1)
        acc += __shfl_xor_sync(0xFFFFFFFFu, acc, off);

    const int lane = threadIdx.x & 31;
    const int wid  = threadIdx.x >> 5;
    if (lane == 0) warp_sums[wid] = acc;
    __syncthreads();

    __shared__ bool is_last;
    if (wid == 0) {
        float v = (lane < THREADS / 32) ? warp_sums[lane] : 0.0f;
#pragma unroll
        for (int off = 4; off > 0; off >>= 1)
            v += __shfl_xor_sync(0xFFFFFFFFu, v, off);
        if (lane == 0) {
            __stcg(&g_partials[blockIdx.x], v);
            __threadfence();
            const int prev = atomicAdd(&g_count, 1);
            is_last = (prev == GRID - 1);
        }
    }
    __syncthreads();

    // ---------- Last block: final reduction (fixed order -> deterministic) ----------
    if (is_last) {
        float v = 0.0f;
        for (int i = threadIdx.x; i < GRID; i += THREADS)
            v += __ldcg(&g_partials[i]);

#pragma unroll
        for (int off = 16; off > 0; off >>= 1)
            v += __shfl_xor_sync(0xFFFFFFFFu, v, off);
        if (lane == 0) warp_sums[wid] = v;
        __syncthreads();

        if (wid == 0) {
            float s = (lane < THREADS / 32) ? warp_sums[lane] : 0.0f;
#pragma unroll
            for (int off = 4; off > 0; off >>= 1)
                s += __shfl_xor_sync(0xFFFFFFFFu, s, off);
            if (lane == 0) {
                out[0] = s * INV_COUNT;
                g_count = 0;
            }
        }
    }
}

extern "C" void kernel_launch(void* const* d_in, const int* in_sizes, int n_in,
                              void* d_out, int out_size)
{
    const float* fwd = (const float*)d_in[0];   // forward_disp  (B,2,H,W) fp32
    const float* bwd = (const float*)d_in[1];   // backward_disp (B,2,H,W) fp32
    float* out = (float*)d_out;

    cyc_loss_fused<<<GRID, THREADS>>>(fwd, bwd, out);
}